// round 5
// baseline (speedup 1.0000x reference)
#include <cuda_runtime.h>

// Scatter (128, 524800) fp32 into upper triangles of (128, 1024, 1024).
// Row-major triu indexing: flat input index of (r,c), c>=r, is
//   base(r) + (c - r),  base(r) = r*M - r*(r-1)/2.
// Pure bandwidth problem: 256 MiB read + 512 MiB write.

#define MATSIZE 1024
#define TRIU_LEN 524800
#define BATCH 128

// One thread per float4 of output. M*M/4 = 262144 float4 per matrix,
// M/4 = 256 float4 per row.
__global__ void __launch_bounds__(256)
triu_scatter_kernel(const float* __restrict__ in, float* __restrict__ out)
{
    const long gid = (long)blockIdx.x * blockDim.x + threadIdx.x;  // float4 index

    const int b   = (int)(gid >> 18);          // / 262144
    const int rem = (int)(gid & 0x3FFFF);      // % 262144
    const int r   = rem >> 8;                  // / 256
    const int c0  = (rem & 0xFF) << 2;         // first of 4 columns

    float4 v;
    if (c0 >= r) {
        // Fully inside the upper triangle: 4 contiguous input floats.
        const int base = r * MATSIZE - ((r * (r - 1)) >> 1);
        const float* p = in + (long)b * TRIU_LEN + base + (c0 - r);
        v.x = p[0]; v.y = p[1]; v.z = p[2]; v.w = p[3];
    } else if (c0 + 3 < r) {
        // Fully below the diagonal.
        v = make_float4(0.f, 0.f, 0.f, 0.f);
    } else {
        // Straddles the diagonal (rare: one thread per row per batch).
        const int base = r * MATSIZE - ((r * (r - 1)) >> 1);
        const float* rowin = in + (long)b * TRIU_LEN + base - r;  // + c gives element
        v.x = (c0     >= r) ? rowin[c0    ] : 0.f;
        v.y = (c0 + 1 >= r) ? rowin[c0 + 1] : 0.f;
        v.z = (c0 + 2 >= r) ? rowin[c0 + 2] : 0.f;
        v.w = (c0 + 3 >= r) ? rowin[c0 + 3] : 0.f;
    }

    reinterpret_cast<float4*>(out)[gid] = v;
}

extern "C" void kernel_launch(void* const* d_in, const int* in_sizes, int n_in,
                              void* d_out, int out_size)
{
    const float* in = (const float*)d_in[0];
    float* out = (float*)d_out;

    const long total4 = (long)BATCH * MATSIZE * MATSIZE / 4;  // 33,554,432
    const int threads = 256;
    const int blocks = (int)(total4 / threads);               // 131,072

    triu_scatter_kernel<<<blocks, threads>>>(in, out);
}